// round 13
// baseline (speedup 1.0000x reference)
#include <cuda_runtime.h>
#include <cstdint>

// Fused SegmentationAugmentation, screen-and-rescue, 2 rows/warp (R13):
//   out[0 .. 2^24)     = trilinear(border) affine sample of input_g   (float)
//   out[2^24 .. 2^25)  = (same sample of label_g) > 0.5               (1.0f/0.0f)
//
// Each warp handles TWO consecutive output rows (b,d,2j) and (b,d,2j+1):
// independent staging loads double memory-level parallelism and the longer
// main loop hides the staging latency that bound R12.
// T = t @ rot(z) => T[0,2] = T[1,2] = 0: x/y pipeline is row-constant.
// BOTH volumes: x/y blend factored per-row into smem -> 2 LDS + 2 FMA/voxel.
// LABEL decision: factored value screens the 0.5 threshold with a 1e-5
// guard band (rounding-difference bound ~2e-6); in-band lanes re-run the
// exact reference rounding chain from gmem.

#define N_VOX (1 << 24)   // 8 * 128^3

__device__ __forceinline__ float unnorm_clamp(float c)
{
    // clip(((c+1)*128 - 1)*0.5, 0, 127) with reference rounding sequence
    return fminf(fmaxf(__fmul_rn(__fsub_rn(__fmul_rn(__fadd_rn(c, 1.0f), 128.0f), 1.0f), 0.5f),
                       0.0f), 127.0f);
}

__global__ __launch_bounds__(256, 5)
void seg_aug_kernel(const float* __restrict__ inp,
                    const float* __restrict__ lab,
                    const float* __restrict__ T,
                    float* __restrict__ out)
{
    __shared__ float s_brow[8][2][128];   // blended input rows per warp (8KB)
    __shared__ float s_lrow[8][2][128];   // blended label rows per warp (8KB)

    const int lane = threadIdx.x & 31;
    const int wid  = threadIdx.x >> 5;
    const int row0 = blockIdx.x * 16 + wid * 2;   // even h; row1 = row0+1 same (b,d)

    const int h0 = row0 & 127;
    const int d  = (row0 >> 7) & 127;
    const int b  = row0 >> 14;

    const float inv128 = 1.0f / 128.0f;
    const float xn  = (2.0f * (float)d + 1.0f) * inv128 - 1.0f;
    const float yn0 = (2.0f * (float)h0 + 1.0f) * inv128 - 1.0f;
    const float yn1 = (2.0f * (float)(h0 + 1) + 1.0f) * inv128 - 1.0f;
    const float zn0 = (2.0f * (float)lane + 1.0f) * inv128 - 1.0f;

    const float t00 = __ldg(T + 0), t01 = __ldg(T + 1), t02 = __ldg(T + 2),  t03 = __ldg(T + 3);
    const float t10 = __ldg(T + 4), t11 = __ldg(T + 5), t12 = __ldg(T + 6),  t13 = __ldg(T + 7);
    const float t20 = __ldg(T + 8), t21 = __ldg(T + 9), t22 = __ldg(T + 10), t23 = __ldg(T + 11);

    const int vol_base = b << 21;
    const bool fastxy = (t02 == 0.0f) && (t12 == 0.0f);   // warp-uniform

    if (fastxy) {
        // per-row uniform x/y pipelines (exact reference prefixes)
        float wx0[2], wx1[2], wy0[2], wy1[2], uzr[2];
        int   r00[2], r10[2], r01[2], r11[2];
        #pragma unroll
        for (int r = 0; r < 2; r++) {
            const float yn = (r == 0) ? yn0 : yn1;
            const float ux = __fadd_rn(__fmul_rn(t00, xn), __fmul_rn(t01, yn));
            const float uy = __fadd_rn(__fmul_rn(t10, xn), __fmul_rn(t11, yn));
            uzr[r] = __fadd_rn(__fmul_rn(t20, xn), __fmul_rn(t21, yn));
            const float X = unnorm_clamp(__fadd_rn(ux, t03));
            const float Y = unnorm_clamp(__fadd_rn(uy, t13));
            const float x0f = floorf(X), y0f = floorf(Y);
            const float fx = __fsub_rn(X, x0f);
            const float fy = __fsub_rn(Y, y0f);
            const int x0 = (int)x0f, y0 = (int)y0f;
            const int x1 = min(x0 + 1, 127);
            const int y1 = min(y0 + 1, 127);
            wx0[r] = __fsub_rn(1.0f, fx); wx1[r] = fx;
            wy0[r] = __fsub_rn(1.0f, fy); wy1[r] = fy;
            r00[r] = vol_base + (x0 << 14) + (y0 << 7);
            r10[r] = vol_base + (x1 << 14) + (y0 << 7);
            r01[r] = vol_base + (x0 << 14) + (y1 << 7);
            r11[r] = vol_base + (x1 << 14) + (y1 << 7);
        }

        // ---- stage blended rows for both output rows, both volumes ----
        // (loads across rows/volumes are independent -> deep MLP)
        #pragma unroll
        for (int r = 0; r < 2; r++) {
            const float wxy00 = wx0[r] * wy0[r];
            const float wxy10 = wx1[r] * wy0[r];
            const float wxy01 = wx0[r] * wy1[r];
            const float wxy11 = wx1[r] * wy1[r];
            // input
            {
                const float4 a = __ldg((const float4*)(inp + r00[r]) + lane);
                const float4 c = __ldg((const float4*)(inp + r10[r]) + lane);
                const float4 e = __ldg((const float4*)(inp + r01[r]) + lane);
                const float4 g = __ldg((const float4*)(inp + r11[r]) + lane);
                float4 bl;
                bl.x = fmaf(a.x, wxy00, fmaf(c.x, wxy10, fmaf(e.x, wxy01, g.x * wxy11)));
                bl.y = fmaf(a.y, wxy00, fmaf(c.y, wxy10, fmaf(e.y, wxy01, g.y * wxy11)));
                bl.z = fmaf(a.z, wxy00, fmaf(c.z, wxy10, fmaf(e.z, wxy01, g.z * wxy11)));
                bl.w = fmaf(a.w, wxy00, fmaf(c.w, wxy10, fmaf(e.w, wxy01, g.w * wxy11)));
                ((float4*)s_brow[wid][r])[lane] = bl;
            }
            // label
            {
                const float4 a = __ldg((const float4*)(lab + r00[r]) + lane);
                const float4 c = __ldg((const float4*)(lab + r10[r]) + lane);
                const float4 e = __ldg((const float4*)(lab + r01[r]) + lane);
                const float4 g = __ldg((const float4*)(lab + r11[r]) + lane);
                float4 bl;
                bl.x = fmaf(a.x, wxy00, fmaf(c.x, wxy10, fmaf(e.x, wxy01, g.x * wxy11)));
                bl.y = fmaf(a.y, wxy00, fmaf(c.y, wxy10, fmaf(e.y, wxy01, g.y * wxy11)));
                bl.z = fmaf(a.z, wxy00, fmaf(c.z, wxy10, fmaf(e.z, wxy01, g.z * wxy11)));
                bl.w = fmaf(a.w, wxy00, fmaf(c.w, wxy10, fmaf(e.w, wxy01, g.w * wxy11)));
                ((float4*)s_lrow[wid][r])[lane] = bl;
            }
        }
        __syncwarp();

        #pragma unroll
        for (int k = 0; k < 4; k++) {
            const float zn = zn0 + 0.5f * (float)k;   // exact (multiples of 2^-7)
            #pragma unroll
            for (int r = 0; r < 2; r++) {
                const float zs = __fadd_rn(__fadd_rn(uzr[r], __fmul_rn(t22, zn)), t23);
                const float Z = unnorm_clamp(zs);
                const float z0f = floorf(Z);
                const float fz = __fsub_rn(Z, z0f);
                const int z0 = (int)z0f;
                const int z1 = min(z0 + 1, 127);
                const float wz0 = __fsub_rn(1.0f, fz), wz1 = fz;

                const int idx = ((row0 + r) << 7) + lane + 32 * k;
                const float* brow = s_brow[wid][r];
                const float* lrow = s_lrow[wid][r];

                // ---- input: 2 LDS + 2 FMA ----
                out[idx] = fmaf(brow[z0], wz0, brow[z1] * wz1);

                // ---- label: fast screen, exact rescue near threshold ----
                const float af = fmaf(lrow[z0], wz0, lrow[z1] * wz1);
                float res = (af > 0.5f) ? 1.0f : 0.0f;
                if (fabsf(af - 0.5f) <= 1e-5f) {
                    const float m00 = __fmul_rn(wz0, wy0[r]);
                    const float m01 = __fmul_rn(wz0, wy1[r]);
                    const float m10 = __fmul_rn(wz1, wy0[r]);
                    const float m11 = __fmul_rn(wz1, wy1[r]);
                    float al = 0.0f;
                    al = __fadd_rn(al, __fmul_rn(__ldg(lab + r00[r] + z0), __fmul_rn(m00, wx0[r])));
                    al = __fadd_rn(al, __fmul_rn(__ldg(lab + r10[r] + z0), __fmul_rn(m00, wx1[r])));
                    al = __fadd_rn(al, __fmul_rn(__ldg(lab + r01[r] + z0), __fmul_rn(m01, wx0[r])));
                    al = __fadd_rn(al, __fmul_rn(__ldg(lab + r11[r] + z0), __fmul_rn(m01, wx1[r])));
                    al = __fadd_rn(al, __fmul_rn(__ldg(lab + r00[r] + z1), __fmul_rn(m10, wx0[r])));
                    al = __fadd_rn(al, __fmul_rn(__ldg(lab + r10[r] + z1), __fmul_rn(m10, wx1[r])));
                    al = __fadd_rn(al, __fmul_rn(__ldg(lab + r01[r] + z1), __fmul_rn(m11, wx0[r])));
                    al = __fadd_rn(al, __fmul_rn(__ldg(lab + r11[r] + z1), __fmul_rn(m11, wx1[r])));
                    res = (al > 0.5f) ? 1.0f : 0.0f;
                }
                out[idx + N_VOX] = res;
            }
        }
    } else {
        // generic exact path (not taken for this transform; kept correct)
        for (int r = 0; r < 2; r++) {
            const int row = row0 + r;
            const float yn = (r == 0) ? yn0 : yn1;
            const float ux = __fadd_rn(__fmul_rn(t00, xn), __fmul_rn(t01, yn));
            const float uy = __fadd_rn(__fmul_rn(t10, xn), __fmul_rn(t11, yn));
            const float uz = __fadd_rn(__fmul_rn(t20, xn), __fmul_rn(t21, yn));
            const int out_base = row << 7;
            #pragma unroll 1
            for (int k = 0; k < 4; k++) {
                const int w = lane + 32 * k;
                const float zn = (2.0f * (float)w + 1.0f) * inv128 - 1.0f;
                const float xs = __fadd_rn(__fadd_rn(ux, __fmul_rn(t02, zn)), t03);
                const float ys = __fadd_rn(__fadd_rn(uy, __fmul_rn(t12, zn)), t13);
                const float zs = __fadd_rn(__fadd_rn(uz, __fmul_rn(t22, zn)), t23);
                const float X = unnorm_clamp(xs);
                const float Y = unnorm_clamp(ys);
                const float Z = unnorm_clamp(zs);
                const float x0f = floorf(X), y0f = floorf(Y), z0f = floorf(Z);
                const float fx = __fsub_rn(X, x0f);
                const float fy = __fsub_rn(Y, y0f);
                const float fz = __fsub_rn(Z, z0f);
                const int x0 = (int)x0f, y0 = (int)y0f, z0 = (int)z0f;
                const int x1 = min(x0 + 1, 127);
                const int y1 = min(y0 + 1, 127);
                const int z1 = min(z0 + 1, 127);
                const float wx0 = __fsub_rn(1.0f, fx), wx1 = fx;
                const float wy0 = __fsub_rn(1.0f, fy), wy1 = fy;
                const float wz0 = __fsub_rn(1.0f, fz), wz1 = fz;

                const int q00 = vol_base + (x0 << 14) + (y0 << 7);
                const int q01 = vol_base + (x0 << 14) + (y1 << 7);
                const int q10 = vol_base + (x1 << 14) + (y0 << 7);
                const int q11 = vol_base + (x1 << 14) + (y1 << 7);

                const float m00 = __fmul_rn(wz0, wy0);
                const float m01 = __fmul_rn(wz0, wy1);
                const float m10 = __fmul_rn(wz1, wy0);
                const float m11 = __fmul_rn(wz1, wy1);

                float ai = 0.0f;
                ai = __fadd_rn(ai, __fmul_rn(__ldg(inp + q00 + z0), __fmul_rn(m00, wx0)));
                ai = __fadd_rn(ai, __fmul_rn(__ldg(inp + q10 + z0), __fmul_rn(m00, wx1)));
                ai = __fadd_rn(ai, __fmul_rn(__ldg(inp + q01 + z0), __fmul_rn(m01, wx0)));
                ai = __fadd_rn(ai, __fmul_rn(__ldg(inp + q11 + z0), __fmul_rn(m01, wx1)));
                ai = __fadd_rn(ai, __fmul_rn(__ldg(inp + q00 + z1), __fmul_rn(m10, wx0)));
                ai = __fadd_rn(ai, __fmul_rn(__ldg(inp + q10 + z1), __fmul_rn(m10, wx1)));
                ai = __fadd_rn(ai, __fmul_rn(__ldg(inp + q01 + z1), __fmul_rn(m11, wx0)));
                ai = __fadd_rn(ai, __fmul_rn(__ldg(inp + q11 + z1), __fmul_rn(m11, wx1)));
                out[out_base + w] = ai;

                float al = 0.0f;
                al = __fadd_rn(al, __fmul_rn(__ldg(lab + q00 + z0), __fmul_rn(m00, wx0)));
                al = __fadd_rn(al, __fmul_rn(__ldg(lab + q10 + z0), __fmul_rn(m00, wx1)));
                al = __fadd_rn(al, __fmul_rn(__ldg(lab + q01 + z0), __fmul_rn(m01, wx0)));
                al = __fadd_rn(al, __fmul_rn(__ldg(lab + q11 + z0), __fmul_rn(m01, wx1)));
                al = __fadd_rn(al, __fmul_rn(__ldg(lab + q00 + z1), __fmul_rn(m10, wx0)));
                al = __fadd_rn(al, __fmul_rn(__ldg(lab + q10 + z1), __fmul_rn(m10, wx1)));
                al = __fadd_rn(al, __fmul_rn(__ldg(lab + q01 + z1), __fmul_rn(m11, wx0)));
                al = __fadd_rn(al, __fmul_rn(__ldg(lab + q11 + z1), __fmul_rn(m11, wx1)));
                out[out_base + w + N_VOX] = (al > 0.5f) ? 1.0f : 0.0f;
            }
        }
    }
}

extern "C" void kernel_launch(void* const* d_in, const int* in_sizes, int n_in,
                              void* d_out, int out_size)
{
    const float* inp = (const float*)d_in[0];   // input_g  [8,1,128,128,128]
    const float* lab = (const float*)d_in[1];   // label_g  [8,1,128,128,128]
    const float* T   = (const float*)d_in[2];   // transform 4x4 (16 floats)
    float* out = (float*)d_out;

    // 131072 rows, 2 rows per warp, 8 warps per block -> 8192 blocks
    seg_aug_kernel<<<8192, 256>>>(inp, lab, T, out);
}

// round 14
// speedup vs baseline: 1.0347x; 1.0347x over previous
#include <cuda_runtime.h>
#include <cstdint>

// Fused SegmentationAugmentation, screen-and-rescue, occ-7 (R14):
//   out[0 .. 2^24)     = trilinear(border) affine sample of input_g   (float)
//   out[2^24 .. 2^25)  = (same sample of label_g) > 0.5               (1.0f/0.0f)
//
// R12 body (1 row/warp, factored blend for both volumes, screen-and-rescue
// label threshold) with __launch_bounds__(256,7): 36 regs -> 56 warps/SM.
// T = t @ rot(z) => T[0,2] = T[1,2] = 0: x/y pipeline is row-constant.
// LABEL decision: factored value screens the 0.5 threshold with a 1e-5
// guard band (rounding-difference bound ~2e-6); in-band lanes re-run the
// exact reference rounding chain from gmem.

#define N_VOX (1 << 24)   // 8 * 128^3

__device__ __forceinline__ float unnorm_clamp(float c)
{
    // clip(((c+1)*128 - 1)*0.5, 0, 127) with reference rounding sequence
    return fminf(fmaxf(__fmul_rn(__fsub_rn(__fmul_rn(__fadd_rn(c, 1.0f), 128.0f), 1.0f), 0.5f),
                       0.0f), 127.0f);
}

__global__ __launch_bounds__(256, 7)
void seg_aug_kernel(const float* __restrict__ inp,
                    const float* __restrict__ lab,
                    const float* __restrict__ T,
                    float* __restrict__ out)
{
    __shared__ float s_brow[8][128];   // blended input row per warp (4KB)
    __shared__ float s_lrow[8][128];   // blended label row per warp (4KB)

    const int lane = threadIdx.x & 31;
    const int wid  = threadIdx.x >> 5;
    const int row  = blockIdx.x * 8 + wid;  // 131072 rows

    const int h = row & 127;
    const int d = (row >> 7) & 127;
    const int b = row >> 14;

    const float inv128 = 1.0f / 128.0f;
    const float xn = (2.0f * (float)d + 1.0f) * inv128 - 1.0f;
    const float yn = (2.0f * (float)h + 1.0f) * inv128 - 1.0f;
    const float zn0 = (2.0f * (float)lane + 1.0f) * inv128 - 1.0f;

    const float t00 = __ldg(T + 0), t01 = __ldg(T + 1), t02 = __ldg(T + 2),  t03 = __ldg(T + 3);
    const float t10 = __ldg(T + 4), t11 = __ldg(T + 5), t12 = __ldg(T + 6),  t13 = __ldg(T + 7);
    const float t20 = __ldg(T + 8), t21 = __ldg(T + 9), t22 = __ldg(T + 10), t23 = __ldg(T + 11);

    // exact reference prefixes (t0*xn + t1*yn), row-constant
    const float ux = __fadd_rn(__fmul_rn(t00, xn), __fmul_rn(t01, yn));
    const float uy = __fadd_rn(__fmul_rn(t10, xn), __fmul_rn(t11, yn));
    const float uz = __fadd_rn(__fmul_rn(t20, xn), __fmul_rn(t21, yn));

    const int out_base = row << 7;
    const int vol_base = b << 21;

    const bool fastxy = (t02 == 0.0f) && (t12 == 0.0f);   // warp-uniform

    if (fastxy) {
        // hoisted x/y pipeline (bit-exact: adding t02*zn = +/-0 can't change
        // the clamped coordinate)
        const float X = unnorm_clamp(__fadd_rn(ux, t03));
        const float Y = unnorm_clamp(__fadd_rn(uy, t13));
        const float x0f = floorf(X), y0f = floorf(Y);
        const float fx = __fsub_rn(X, x0f);
        const float fy = __fsub_rn(Y, y0f);
        const int x0 = (int)x0f, y0 = (int)y0f;
        const int x1 = min(x0 + 1, 127);
        const int y1 = min(y0 + 1, 127);
        const float wx0 = __fsub_rn(1.0f, fx), wx1 = fx;
        const float wy0 = __fsub_rn(1.0f, fy), wy1 = fy;

        // warp-uniform row offsets
        const int r00 = vol_base + (x0 << 14) + (y0 << 7);  // (x0,y0)
        const int r10 = vol_base + (x1 << 14) + (y0 << 7);  // (x1,y0)
        const int r01 = vol_base + (x0 << 14) + (y1 << 7);  // (x0,y1)
        const int r11 = vol_base + (x1 << 14) + (y1 << 7);  // (x1,y1)

        const float wxy00 = wx0 * wy0;
        const float wxy10 = wx1 * wy0;
        const float wxy01 = wx0 * wy1;
        const float wxy11 = wx1 * wy1;

        // ---- stage blended INPUT row (two-phase, low live temps) ----
        {
            float4 bl;
            {
                const float4 a = __ldg((const float4*)(inp + r00) + lane);
                const float4 c = __ldg((const float4*)(inp + r10) + lane);
                bl.x = fmaf(a.x, wxy00, c.x * wxy10);
                bl.y = fmaf(a.y, wxy00, c.y * wxy10);
                bl.z = fmaf(a.z, wxy00, c.z * wxy10);
                bl.w = fmaf(a.w, wxy00, c.w * wxy10);
            }
            {
                const float4 e = __ldg((const float4*)(inp + r01) + lane);
                const float4 g = __ldg((const float4*)(inp + r11) + lane);
                bl.x = fmaf(e.x, wxy01, fmaf(g.x, wxy11, bl.x));
                bl.y = fmaf(e.y, wxy01, fmaf(g.y, wxy11, bl.y));
                bl.z = fmaf(e.z, wxy01, fmaf(g.z, wxy11, bl.z));
                bl.w = fmaf(e.w, wxy01, fmaf(g.w, wxy11, bl.w));
            }
            ((float4*)s_brow[wid])[lane] = bl;
        }
        // ---- stage blended LABEL row (same structure) ----
        {
            float4 bl;
            {
                const float4 a = __ldg((const float4*)(lab + r00) + lane);
                const float4 c = __ldg((const float4*)(lab + r10) + lane);
                bl.x = fmaf(a.x, wxy00, c.x * wxy10);
                bl.y = fmaf(a.y, wxy00, c.y * wxy10);
                bl.z = fmaf(a.z, wxy00, c.z * wxy10);
                bl.w = fmaf(a.w, wxy00, c.w * wxy10);
            }
            {
                const float4 e = __ldg((const float4*)(lab + r01) + lane);
                const float4 g = __ldg((const float4*)(lab + r11) + lane);
                bl.x = fmaf(e.x, wxy01, fmaf(g.x, wxy11, bl.x));
                bl.y = fmaf(e.y, wxy01, fmaf(g.y, wxy11, bl.y));
                bl.z = fmaf(e.z, wxy01, fmaf(g.z, wxy11, bl.z));
                bl.w = fmaf(e.w, wxy01, fmaf(g.w, wxy11, bl.w));
            }
            ((float4*)s_lrow[wid])[lane] = bl;
        }
        __syncwarp();

        const float* brow = s_brow[wid];
        const float* lrow = s_lrow[wid];

        #pragma unroll
        for (int k = 0; k < 4; k++) {
            const float zn = zn0 + 0.5f * (float)k;   // exact (multiples of 2^-7)
            const float zs = __fadd_rn(__fadd_rn(uz, __fmul_rn(t22, zn)), t23);
            const float Z = unnorm_clamp(zs);
            const float z0f = floorf(Z);
            const float fz = __fsub_rn(Z, z0f);
            const int z0 = (int)z0f;
            const int z1 = min(z0 + 1, 127);
            const float wz0 = __fsub_rn(1.0f, fz), wz1 = fz;

            const int idx = out_base + lane + 32 * k;

            // ---- input: 2 LDS + 2 FMA ----
            out[idx] = fmaf(brow[z0], wz0, brow[z1] * wz1);

            // ---- label: fast screen, exact rescue near the threshold ----
            const float af = fmaf(lrow[z0], wz0, lrow[z1] * wz1);
            float res = (af > 0.5f) ? 1.0f : 0.0f;
            if (fabsf(af - 0.5f) <= 1e-5f) {
                // exact reference rounding chain from gmem (rare)
                const float m00 = __fmul_rn(wz0, wy0);
                const float m01 = __fmul_rn(wz0, wy1);
                const float m10 = __fmul_rn(wz1, wy0);
                const float m11 = __fmul_rn(wz1, wy1);
                float al = 0.0f;
                al = __fadd_rn(al, __fmul_rn(__ldg(lab + r00 + z0), __fmul_rn(m00, wx0)));
                al = __fadd_rn(al, __fmul_rn(__ldg(lab + r10 + z0), __fmul_rn(m00, wx1)));
                al = __fadd_rn(al, __fmul_rn(__ldg(lab + r01 + z0), __fmul_rn(m01, wx0)));
                al = __fadd_rn(al, __fmul_rn(__ldg(lab + r11 + z0), __fmul_rn(m01, wx1)));
                al = __fadd_rn(al, __fmul_rn(__ldg(lab + r00 + z1), __fmul_rn(m10, wx0)));
                al = __fadd_rn(al, __fmul_rn(__ldg(lab + r10 + z1), __fmul_rn(m10, wx1)));
                al = __fadd_rn(al, __fmul_rn(__ldg(lab + r01 + z1), __fmul_rn(m11, wx0)));
                al = __fadd_rn(al, __fmul_rn(__ldg(lab + r11 + z1), __fmul_rn(m11, wx1)));
                res = (al > 0.5f) ? 1.0f : 0.0f;
            }
            out[idx + N_VOX] = res;
        }
    } else {
        // generic exact path (not taken for this transform; kept correct)
        #pragma unroll 1
        for (int k = 0; k < 4; k++) {
            const int w = lane + 32 * k;
            const float zn = (2.0f * (float)w + 1.0f) * inv128 - 1.0f;
            const float xs = __fadd_rn(__fadd_rn(ux, __fmul_rn(t02, zn)), t03);
            const float ys = __fadd_rn(__fadd_rn(uy, __fmul_rn(t12, zn)), t13);
            const float zs = __fadd_rn(__fadd_rn(uz, __fmul_rn(t22, zn)), t23);
            const float X = unnorm_clamp(xs);
            const float Y = unnorm_clamp(ys);
            const float Z = unnorm_clamp(zs);
            const float x0f = floorf(X), y0f = floorf(Y), z0f = floorf(Z);
            const float fx = __fsub_rn(X, x0f);
            const float fy = __fsub_rn(Y, y0f);
            const float fz = __fsub_rn(Z, z0f);
            const int x0 = (int)x0f, y0 = (int)y0f, z0 = (int)z0f;
            const int x1 = min(x0 + 1, 127);
            const int y1 = min(y0 + 1, 127);
            const int z1 = min(z0 + 1, 127);
            const float wx0 = __fsub_rn(1.0f, fx), wx1 = fx;
            const float wy0 = __fsub_rn(1.0f, fy), wy1 = fy;
            const float wz0 = __fsub_rn(1.0f, fz), wz1 = fz;

            const int r00 = vol_base + (x0 << 14) + (y0 << 7);
            const int r01 = vol_base + (x0 << 14) + (y1 << 7);
            const int r10 = vol_base + (x1 << 14) + (y0 << 7);
            const int r11 = vol_base + (x1 << 14) + (y1 << 7);

            const float m00 = __fmul_rn(wz0, wy0);
            const float m01 = __fmul_rn(wz0, wy1);
            const float m10 = __fmul_rn(wz1, wy0);
            const float m11 = __fmul_rn(wz1, wy1);

            float ai = 0.0f;
            ai = __fadd_rn(ai, __fmul_rn(__ldg(inp + r00 + z0), __fmul_rn(m00, wx0)));
            ai = __fadd_rn(ai, __fmul_rn(__ldg(inp + r10 + z0), __fmul_rn(m00, wx1)));
            ai = __fadd_rn(ai, __fmul_rn(__ldg(inp + r01 + z0), __fmul_rn(m01, wx0)));
            ai = __fadd_rn(ai, __fmul_rn(__ldg(inp + r11 + z0), __fmul_rn(m01, wx1)));
            ai = __fadd_rn(ai, __fmul_rn(__ldg(inp + r00 + z1), __fmul_rn(m10, wx0)));
            ai = __fadd_rn(ai, __fmul_rn(__ldg(inp + r10 + z1), __fmul_rn(m10, wx1)));
            ai = __fadd_rn(ai, __fmul_rn(__ldg(inp + r01 + z1), __fmul_rn(m11, wx0)));
            ai = __fadd_rn(ai, __fmul_rn(__ldg(inp + r11 + z1), __fmul_rn(m11, wx1)));
            out[out_base + w] = ai;

            float al = 0.0f;
            al = __fadd_rn(al, __fmul_rn(__ldg(lab + r00 + z0), __fmul_rn(m00, wx0)));
            al = __fadd_rn(al, __fmul_rn(__ldg(lab + r10 + z0), __fmul_rn(m00, wx1)));
            al = __fadd_rn(al, __fmul_rn(__ldg(lab + r01 + z0), __fmul_rn(m01, wx0)));
            al = __fadd_rn(al, __fmul_rn(__ldg(lab + r11 + z0), __fmul_rn(m01, wx1)));
            al = __fadd_rn(al, __fmul_rn(__ldg(lab + r00 + z1), __fmul_rn(m10, wx0)));
            al = __fadd_rn(al, __fmul_rn(__ldg(lab + r10 + z1), __fmul_rn(m10, wx1)));
            al = __fadd_rn(al, __fmul_rn(__ldg(lab + r01 + z1), __fmul_rn(m11, wx0)));
            al = __fadd_rn(al, __fmul_rn(__ldg(lab + r11 + z1), __fmul_rn(m11, wx1)));
            out[out_base + w + N_VOX] = (al > 0.5f) ? 1.0f : 0.0f;
        }
    }
}

extern "C" void kernel_launch(void* const* d_in, const int* in_sizes, int n_in,
                              void* d_out, int out_size)
{
    const float* inp = (const float*)d_in[0];   // input_g  [8,1,128,128,128]
    const float* lab = (const float*)d_in[1];   // label_g  [8,1,128,128,128]
    const float* T   = (const float*)d_in[2];   // transform 4x4 (16 floats)
    float* out = (float*)d_out;

    // 131072 rows, 8 rows (warps) per block
    seg_aug_kernel<<<16384, 256>>>(inp, lab, T, out);
}